// round 14
// baseline (speedup 1.0000x reference)
#include <cuda_runtime.h>
#include <cuda_bf16.h>
#include <cstdint>

// ---------------------------------------------------------------------------
// LGNInputLayerCell: i_in[post] += weights[s] * (inputs_t[pre[s]] > 0)
//   d_in[0] : int32  inputs_t [N_SOURCE]   (17400)
//   d_in[1] : int32  indices  [N_SYN, 2]   (post, pre) interleaved
//   d_in[2] : float  weights  [N_SYN]
//   d_in[3] : int32  n_post   (unused; out_size == n_post)
// output: float [n_post]
//
// R13 established the scattered-RED wavefront floor (~111us for seg_sum;
// batching/occupancy/TMA/L2-policy all neutral). The only removable cost is
// the serialized prologue + launch gap (~2-4us). This round overlaps it with
// PDL: seg_sum launches programmatically-dependent, issues its independent
// streaming loads immediately, and grid-dep-syncs only before consuming the
// mask / issuing REDs.
// ---------------------------------------------------------------------------

#define MASK_WORDS_MAX 2048     // 65536 sources capacity (17400 -> 544 words)
__device__ unsigned int g_active_mask[MASK_WORDS_MAX];

#define THREADS 512

// ---------------------------------------------------------------------------
// Prologue: build active bitmask (ballot) + zero the poisoned output.
// Fires the programmatic-launch trigger at the end so the dependent seg_sum
// grid can begin scheduling while this grid drains.
// ---------------------------------------------------------------------------
__global__ void prologue_kernel(const int* __restrict__ inputs_t,
                                int n_source,
                                float* __restrict__ out, int n_post) {
    const int i = blockIdx.x * blockDim.x + threadIdx.x;

    const int n_src32 = (n_source + 31) & ~31;
    if (i < n_src32) {
        int v = (i < n_source) ? inputs_t[i] : 0;
        unsigned int b = __ballot_sync(0xffffffffu, v > 0);
        if ((threadIdx.x & 31) == 0) g_active_mask[i >> 5] = b;
    }

    const int base = i << 2;
    if (base + 3 < n_post) {
        *reinterpret_cast<float4*>(out + base) = make_float4(0.f, 0.f, 0.f, 0.f);
    } else if (base < n_post) {
        for (int j = base; j < n_post; ++j) out[j] = 0.0f;
    }

    cudaTriggerProgrammaticLaunchCompletion();
}

// ---------------------------------------------------------------------------
// Main scatter-reduce: flat grid, 8 synapses/thread (proven R8 form).
//   4x int4 + 2x float4 front-batched BEFORE the grid-dependency sync
//   (independent of the prologue), then mask staging + predicated REDs after.
// ---------------------------------------------------------------------------
__global__ __launch_bounds__(THREADS)
void seg_sum_kernel(const int* __restrict__ indices,
                    const float* __restrict__ weights,
                    float* __restrict__ out,
                    int n_syn, int n_words) {
    const int tid  = threadIdx.x;
    const int i    = blockIdx.x * blockDim.x + tid;
    const int base = i << 3;                   // 8 synapses per thread
    const bool full = (base + 8 <= n_syn);

    // -- phase 1: issue streaming loads (do NOT depend on the prologue) --
    int4   a0, a1, a2, a3;
    float4 w0, w1;
    if (full) {
        const int4*   idx4 = reinterpret_cast<const int4*>(indices);
        const float4* w4   = reinterpret_cast<const float4*>(weights);
        a0 = __ldg(&idx4[4 * i + 0]);          // (post0,pre0,post1,pre1)
        a1 = __ldg(&idx4[4 * i + 1]);
        a2 = __ldg(&idx4[4 * i + 2]);
        a3 = __ldg(&idx4[4 * i + 3]);
        w0 = __ldg(&w4[2 * i + 0]);
        w1 = __ldg(&w4[2 * i + 1]);
    }

    // -- phase 2: wait for the prologue's writes (mask + zeroed out) --
    cudaGridDependencySynchronize();

    __shared__ unsigned int s_mask[MASK_WORDS_MAX];
    {
        const int n_w4 = (n_words + 3) >> 2;
        int4* s4 = reinterpret_cast<int4*>(s_mask);
        const int4* g4 = reinterpret_cast<const int4*>(g_active_mask);
        for (int w = tid; w < n_w4; w += THREADS) s4[w] = g4[w];
    }
    __syncthreads();

    if (base >= n_syn) return;

    if (full) {
        const unsigned int m0 = s_mask[((unsigned)a0.y) >> 5];
        const unsigned int m1 = s_mask[((unsigned)a0.w) >> 5];
        const unsigned int m2 = s_mask[((unsigned)a1.y) >> 5];
        const unsigned int m3 = s_mask[((unsigned)a1.w) >> 5];
        const unsigned int m4 = s_mask[((unsigned)a2.y) >> 5];
        const unsigned int m5 = s_mask[((unsigned)a2.w) >> 5];
        const unsigned int m6 = s_mask[((unsigned)a3.y) >> 5];
        const unsigned int m7 = s_mask[((unsigned)a3.w) >> 5];

        if ((m0 >> (a0.y & 31)) & 1u) atomicAdd(out + a0.x, w0.x);
        if ((m1 >> (a0.w & 31)) & 1u) atomicAdd(out + a0.z, w0.y);
        if ((m2 >> (a1.y & 31)) & 1u) atomicAdd(out + a1.x, w0.z);
        if ((m3 >> (a1.w & 31)) & 1u) atomicAdd(out + a1.z, w0.w);
        if ((m4 >> (a2.y & 31)) & 1u) atomicAdd(out + a2.x, w1.x);
        if ((m5 >> (a2.w & 31)) & 1u) atomicAdd(out + a2.z, w1.y);
        if ((m6 >> (a3.y & 31)) & 1u) atomicAdd(out + a3.x, w1.z);
        if ((m7 >> (a3.w & 31)) & 1u) atomicAdd(out + a3.z, w1.w);
    } else {
        // scalar tail (last partial group of < 8 synapses)
        for (int j = base; j < n_syn; ++j) {
            int post = indices[2 * j];
            int pre  = indices[2 * j + 1];
            unsigned int m = s_mask[((unsigned)pre) >> 5];
            if ((m >> (pre & 31)) & 1u) atomicAdd(out + post, weights[j]);
        }
    }
}

extern "C" void kernel_launch(void* const* d_in, const int* in_sizes, int n_in,
                              void* d_out, int out_size) {
    const int*   inputs_t = (const int*)d_in[0];
    const int*   indices  = (const int*)d_in[1];
    const float* weights  = (const float*)d_in[2];
    float*       out      = (float*)d_out;

    const int n_source = in_sizes[0];
    const int n_syn    = in_sizes[2];
    const int n_post   = out_size;

    // 1) fused prologue: bitmask + output zeroing
    {
        const int n_src32   = (n_source + 31) & ~31;
        const int n_zero_th = (n_post + 3) >> 2;
        const int n_thr     = (n_src32 > n_zero_th) ? n_src32 : n_zero_th;
        prologue_kernel<<<(n_thr + 255) / 256, 256>>>(inputs_t, n_source, out, n_post);
    }

    // 2) scatter-reduce, launched with programmatic dependency on the
    //    prologue so its load-issue phase overlaps the prologue's tail.
    const int n_words = (n_source + 31) >> 5;   // 544 (< 2048)
    const int groups  = (n_syn + 7) >> 3;
    if (groups > 0) {
        cudaLaunchConfig_t cfg = {};
        cfg.gridDim  = dim3((groups + THREADS - 1) / THREADS);
        cfg.blockDim = dim3(THREADS);
        cfg.dynamicSmemBytes = 0;
        cfg.stream = 0;                          // captured stream (legacy default)
        cudaLaunchAttribute at[1];
        at[0].id = cudaLaunchAttributeProgrammaticStreamSerialization;
        at[0].val.programmaticStreamSerializationAllowed = 1;
        cfg.attrs = at;
        cfg.numAttrs = 1;
        cudaLaunchKernelEx(&cfg, seg_sum_kernel,
                           indices, weights, out, n_syn, n_words);
    }
}

// round 16
// speedup vs baseline: 1.0219x; 1.0219x over previous
#include <cuda_runtime.h>
#include <cuda_bf16.h>
#include <cstdint>

// ---------------------------------------------------------------------------
// LGNInputLayerCell: i_in[post] += weights[s] * (inputs_t[pre[s]] > 0)
//   d_in[0] : int32  inputs_t [N_SOURCE]   (17400)
//   d_in[1] : int32  indices  [N_SYN, 2]   (post, pre) interleaved
//   d_in[2] : float  weights  [N_SYN]
//   d_in[3] : int32  n_post   (unused; out_size == n_post)
// output: float [n_post]
//
// R14 showed PDL works but holding loads across the grid-dep-sync cost 25
// registers (occ 60->46%) and ate the gain. R15: PDL retained, but the
// dependency sync is the FIRST instruction — the kernel body is the proven
// 39-reg R8 form. PDL now hides only the prologue drain + launch ramp
// (~2.2us measured serialization cost in R13).
// ---------------------------------------------------------------------------

#define MASK_WORDS_MAX 2048     // 65536 sources capacity (17400 -> 544 words)
__device__ unsigned int g_active_mask[MASK_WORDS_MAX];

#define THREADS 512

// ---------------------------------------------------------------------------
// Prologue: build active bitmask (ballot) + zero the poisoned output.
// Fires the programmatic-launch trigger at the end.
// ---------------------------------------------------------------------------
__global__ void prologue_kernel(const int* __restrict__ inputs_t,
                                int n_source,
                                float* __restrict__ out, int n_post) {
    const int i = blockIdx.x * blockDim.x + threadIdx.x;

    const int n_src32 = (n_source + 31) & ~31;
    if (i < n_src32) {
        int v = (i < n_source) ? inputs_t[i] : 0;
        unsigned int b = __ballot_sync(0xffffffffu, v > 0);
        if ((threadIdx.x & 31) == 0) g_active_mask[i >> 5] = b;
    }

    const int base = i << 2;
    if (base + 3 < n_post) {
        *reinterpret_cast<float4*>(out + base) = make_float4(0.f, 0.f, 0.f, 0.f);
    } else if (base < n_post) {
        for (int j = base; j < n_post; ++j) out[j] = 0.0f;
    }

    cudaTriggerProgrammaticLaunchCompletion();
}

// ---------------------------------------------------------------------------
// Main scatter-reduce: flat grid, 8 synapses/thread (proven R8 form).
// Grid-dependency sync FIRST (no registers held across it), then the
// unchanged 39-reg body: mask->SMEM, 6 front-batched LDG.128, 8 predicated
// REDs. Scalar fallback handles the final partial group.
// ---------------------------------------------------------------------------
__global__ __launch_bounds__(THREADS)
void seg_sum_kernel(const int* __restrict__ indices,
                    const float* __restrict__ weights,
                    float* __restrict__ out,
                    int n_syn, int n_words) {
    // wait for prologue (mask + zeroed out) before ANY dependent work;
    // placed first so no state is live across it -> no register cost.
    cudaGridDependencySynchronize();

    __shared__ unsigned int s_mask[MASK_WORDS_MAX];
    {
        const int n_w4 = (n_words + 3) >> 2;
        int4* s4 = reinterpret_cast<int4*>(s_mask);
        const int4* g4 = reinterpret_cast<const int4*>(g_active_mask);
        for (int w = threadIdx.x; w < n_w4; w += THREADS) s4[w] = g4[w];
    }
    __syncthreads();

    const int i    = blockIdx.x * blockDim.x + threadIdx.x;
    const int base = i << 3;                   // 8 synapses per thread
    if (base >= n_syn) return;

    if (base + 8 <= n_syn) {
        const int4*   idx4 = reinterpret_cast<const int4*>(indices);
        const float4* w4   = reinterpret_cast<const float4*>(weights);

        // 6 independent streaming loads, front-batched (MLP 6).
        int4   a0 = __ldg(&idx4[4 * i + 0]);   // (post0,pre0,post1,pre1)
        int4   a1 = __ldg(&idx4[4 * i + 1]);
        int4   a2 = __ldg(&idx4[4 * i + 2]);
        int4   a3 = __ldg(&idx4[4 * i + 3]);
        float4 w0 = __ldg(&w4[2 * i + 0]);
        float4 w1 = __ldg(&w4[2 * i + 1]);

        const unsigned int m0 = s_mask[((unsigned)a0.y) >> 5];
        const unsigned int m1 = s_mask[((unsigned)a0.w) >> 5];
        const unsigned int m2 = s_mask[((unsigned)a1.y) >> 5];
        const unsigned int m3 = s_mask[((unsigned)a1.w) >> 5];
        const unsigned int m4 = s_mask[((unsigned)a2.y) >> 5];
        const unsigned int m5 = s_mask[((unsigned)a2.w) >> 5];
        const unsigned int m6 = s_mask[((unsigned)a3.y) >> 5];
        const unsigned int m7 = s_mask[((unsigned)a3.w) >> 5];

        if ((m0 >> (a0.y & 31)) & 1u) atomicAdd(out + a0.x, w0.x);
        if ((m1 >> (a0.w & 31)) & 1u) atomicAdd(out + a0.z, w0.y);
        if ((m2 >> (a1.y & 31)) & 1u) atomicAdd(out + a1.x, w0.z);
        if ((m3 >> (a1.w & 31)) & 1u) atomicAdd(out + a1.z, w0.w);
        if ((m4 >> (a2.y & 31)) & 1u) atomicAdd(out + a2.x, w1.x);
        if ((m5 >> (a2.w & 31)) & 1u) atomicAdd(out + a2.z, w1.y);
        if ((m6 >> (a3.y & 31)) & 1u) atomicAdd(out + a3.x, w1.z);
        if ((m7 >> (a3.w & 31)) & 1u) atomicAdd(out + a3.z, w1.w);
    } else {
        // scalar tail (last partial group of < 8 synapses)
        for (int j = base; j < n_syn; ++j) {
            int post = indices[2 * j];
            int pre  = indices[2 * j + 1];
            unsigned int m = s_mask[((unsigned)pre) >> 5];
            if ((m >> (pre & 31)) & 1u) atomicAdd(out + post, weights[j]);
        }
    }
}

extern "C" void kernel_launch(void* const* d_in, const int* in_sizes, int n_in,
                              void* d_out, int out_size) {
    const int*   inputs_t = (const int*)d_in[0];
    const int*   indices  = (const int*)d_in[1];
    const float* weights  = (const float*)d_in[2];
    float*       out      = (float*)d_out;

    const int n_source = in_sizes[0];
    const int n_syn    = in_sizes[2];
    const int n_post   = out_size;

    // 1) fused prologue: bitmask + output zeroing
    {
        const int n_src32   = (n_source + 31) & ~31;
        const int n_zero_th = (n_post + 3) >> 2;
        const int n_thr     = (n_src32 > n_zero_th) ? n_src32 : n_zero_th;
        prologue_kernel<<<(n_thr + 255) / 256, 256>>>(inputs_t, n_source, out, n_post);
    }

    // 2) scatter-reduce with programmatic dependency: grid spins up while the
    //    prologue drains; correctness preserved by grid-dep-sync at kernel top.
    const int n_words = (n_source + 31) >> 5;   // 544 (< 2048)
    const int groups  = (n_syn + 7) >> 3;
    if (groups > 0) {
        cudaLaunchConfig_t cfg = {};
        cfg.gridDim  = dim3((groups + THREADS - 1) / THREADS);
        cfg.blockDim = dim3(THREADS);
        cfg.dynamicSmemBytes = 0;
        cfg.stream = 0;
        cudaLaunchAttribute at[1];
        at[0].id = cudaLaunchAttributeProgrammaticStreamSerialization;
        at[0].val.programmaticStreamSerializationAllowed = 1;
        cfg.attrs = at;
        cfg.numAttrs = 1;
        cudaLaunchKernelEx(&cfg, seg_sum_kernel,
                           indices, weights, out, n_syn, n_words);
    }
}